// round 4
// baseline (speedup 1.0000x reference)
#include <cuda_runtime.h>

#define N_NODES 100000
#define N_EDGES 1600000
#define F 128
#define SCAN_B 196      // ceil(100001 / 512)
#define TILE 96
#define THREADS 384
#define LAYER_BLOCKS ((N_NODES + TILE - 1) / TILE)   // 1042
#define W_VEC4 (F * F / 4)                           // 4096 float4 per weight
#define W_FULL_IT (W_VEC4 / THREADS)                 // 10
#define W_TAIL (W_VEC4 - W_FULL_IT * THREADS)        // 256

// ---------------- scratch (static device globals; no cudaMalloc) ------------
__device__ __align__(16) int g_cnt[N_NODES + 1];   // zero-init; scan1 re-zeroes
__device__ __align__(16) int g_off[N_NODES + 1];
__device__ __align__(16) int g_cur[N_NODES];
__device__ __align__(16) int g_csr[N_EDGES];
__device__ __align__(16) int g_part[SCAN_B];
__device__ __align__(16) float g_a[(size_t)N_NODES * F];
__device__ __align__(16) float g_b[(size_t)N_NODES * F];

// ---------------- f32x2 helpers ----------------------------------------------
__device__ __forceinline__ unsigned long long pk2(float a, float b) {
    unsigned long long r;
    asm("mov.b64 %0, {%1, %2};" : "=l"(r) : "f"(a), "f"(b));
    return r;
}
__device__ __forceinline__ void fma2(unsigned long long& d,
                                     unsigned long long a, unsigned long long b) {
    asm("fma.rn.f32x2 %0, %1, %2, %0;" : "+l"(d) : "l"(a), "l"(b));
}
__device__ __forceinline__ float fold2(unsigned long long v) {
    float lo, hi;
    asm("mov.b64 {%0, %1}, %2;" : "=f"(lo), "=f"(hi) : "l"(v));
    return lo + hi;
}

// ---------------- cp.async helpers --------------------------------------------
__device__ __forceinline__ void cp16(unsigned smem_addr, const void* gptr) {
    asm volatile("cp.async.cg.shared.global [%0], [%1], 16;" ::
                 "r"(smem_addr), "l"(gptr));
}
__device__ __forceinline__ void cp_commit() {
    asm volatile("cp.async.commit_group;");
}
__device__ __forceinline__ void cp_wait1() {
    asm volatile("cp.async.wait_group 1;");
}
__device__ __forceinline__ void cp_wait0() {
    asm volatile("cp.async.wait_group 0;");
}

// ---------------- edge dtype: block-local detection ---------------------------
// Under int64 (LE), high words of values < 100000 are all 0. Under int32 the
// sampled words are real node ids; 256 consecutive all-zero ids ~ impossible.
__device__ __forceinline__ int block_is64(const void* ei, int e) {
    unsigned hw = ((const unsigned*)ei)[2 * e + 1];
    int any = __syncthreads_or(hw != 0u);
    return any ? 0 : 1;
}

// ---------------- CSR build ----------------------------------------------------
__global__ void k_count(const void* __restrict__ ei) {
    int e = blockIdx.x * 256 + threadIdx.x;
    int is64 = block_is64(ei, e);
    int d = is64 ? (int)(((const long long*)ei)[N_EDGES + e])
                 : ((const int*)ei)[N_EDGES + e];
    atomicAdd(&g_cnt[d + 1], 1);
}

__global__ void k_scan1() {
    __shared__ int wsum[16];
    int tid = threadIdx.x;
    int i = blockIdx.x * 512 + tid;
    int lane = tid & 31, w = tid >> 5;
    int s = (i <= N_NODES) ? g_cnt[i] : 0;
    if (i <= N_NODES) g_cnt[i] = 0;                   // restore invariant
    #pragma unroll
    for (int o = 1; o < 32; o <<= 1) {
        int t = __shfl_up_sync(0xffffffffu, s, o);
        if (lane >= o) s += t;
    }
    if (lane == 31) wsum[w] = s;
    __syncthreads();
    if (w == 0) {
        int ws = (lane < 16) ? wsum[lane] : 0;
        #pragma unroll
        for (int o = 1; o < 16; o <<= 1) {
            int t = __shfl_up_sync(0xffffffffu, ws, o);
            if (lane >= o) ws += t;
        }
        if (lane < 16) wsum[lane] = ws;
    }
    __syncthreads();
    int incl = s + (w > 0 ? wsum[w - 1] : 0);
    if (i <= N_NODES) g_off[i] = incl;
    if (tid == 511) g_part[blockIdx.x] = incl;
}

__global__ void k_scan2() {
    __shared__ int wsum[8];
    int tid = threadIdx.x;
    int lane = tid & 31, w = tid >> 5;
    int s = (tid < SCAN_B) ? g_part[tid] : 0;
    #pragma unroll
    for (int o = 1; o < 32; o <<= 1) {
        int t = __shfl_up_sync(0xffffffffu, s, o);
        if (lane >= o) s += t;
    }
    if (lane == 31) wsum[w] = s;
    __syncthreads();
    if (w == 0) {
        int ws = (lane < 8) ? wsum[lane] : 0;
        #pragma unroll
        for (int o = 1; o < 8; o <<= 1) {
            int t = __shfl_up_sync(0xffffffffu, ws, o);
            if (lane >= o) ws += t;
        }
        if (lane < 8) wsum[lane] = ws;
    }
    __syncthreads();
    int incl = s + (w > 0 ? wsum[w - 1] : 0);
    if (tid < SCAN_B) g_part[tid] = incl;
}

__global__ void k_scan3() {
    int b = blockIdx.x;
    int i = b * 512 + threadIdx.x;
    if (i <= N_NODES) {
        int v = g_off[i] + (b > 0 ? g_part[b - 1] : 0);
        g_off[i] = v;
        if (i < N_NODES) g_cur[i] = v;
    }
}

__global__ void k_fill(const void* __restrict__ ei) {
    int e = blockIdx.x * 256 + threadIdx.x;
    int is64 = block_is64(ei, e);
    int s, d;
    if (is64) {
        s = (int)(((const long long*)ei)[e]);
        d = (int)(((const long long*)ei)[N_EDGES + e]);
    } else {
        s = ((const int*)ei)[e];
        d = ((const int*)ei)[N_EDGES + e];
    }
    int p = atomicAdd(&g_cur[d], 1);
    g_csr[p] = s;
}

// ---------------- fused GIN layer ----------------------------------------------
// in_sel: 0=x(ptr arg), 1=g_a, 2=g_b ; out_sel: 1=g_a, 2=g_b, 3=outS (scalar dot)
__global__ void __launch_bounds__(THREADS, 1)
k_layer(const float* __restrict__ xin,
        const float* __restrict__ W1, const float* __restrict__ b1,
        const float* __restrict__ W2, const float* __restrict__ b2,
        int in_sel, int out_sel, const float* __restrict__ b32,
        float* __restrict__ outS) {
    extern __shared__ float smem[];
    float* sW1 = smem;                 // 128x128
    float* sW2 = smem + F * F;         // 128x128 (or w32 in first 128 floats)
    float* sT  = smem + 2 * F * F;     // 96x128
    float* sH  = sT + TILE * F;        // 96x128

    const float* in = (in_sel == 0) ? xin : (in_sel == 1 ? (const float*)g_a
                                                         : (const float*)g_b);
    int last = (out_sel == 3);
    float* outF = (out_sel == 1) ? (float*)g_a : (float*)g_b;

    int tid = threadIdx.x;
    int nbase = blockIdx.x * TILE;
    int lane = tid & 31;
    int w = tid >> 5;

    // ---- stream weights into smem: 4096 float4 per matrix ----
    unsigned sW1a = (unsigned)__cvta_generic_to_shared(sW1);
    unsigned sW2a = (unsigned)__cvta_generic_to_shared(sW2);
    #pragma unroll
    for (int i = 0; i < W_FULL_IT; i++)
        cp16(sW1a + (tid + i * THREADS) * 16, (const float4*)W1 + tid + i * THREADS);
    if (tid < W_TAIL)
        cp16(sW1a + (tid + W_FULL_IT * THREADS) * 16,
             (const float4*)W1 + tid + W_FULL_IT * THREADS);
    cp_commit();
    if (!last) {
        #pragma unroll
        for (int i = 0; i < W_FULL_IT; i++)
            cp16(sW2a + (tid + i * THREADS) * 16, (const float4*)W2 + tid + i * THREADS);
        if (tid < W_TAIL)
            cp16(sW2a + (tid + W_FULL_IT * THREADS) * 16,
                 (const float4*)W2 + tid + W_FULL_IT * THREADS);
    } else {
        if (tid < 32) cp16(sW2a + tid * 16, (const float4*)W2 + tid);  // w32: 128 floats
    }
    cp_commit();

    // ---- Phase A: gather t = in[node] + sum_neighbors into sT ----
    const float4* in4 = (const float4*)in;
    #pragma unroll 1
    for (int i = 0; i < 8; i++) {
        int ln = w * 8 + i;
        int node = nbase + ln;
        float4 acc = make_float4(0.f, 0.f, 0.f, 0.f);
        if (node < N_NODES) {
            acc = in4[(size_t)node * 32 + lane];
            int e = g_off[node], end = g_off[node + 1];
            for (; e + 8 <= end; e += 8) {
                int s0 = g_csr[e],     s1 = g_csr[e + 1];
                int s2 = g_csr[e + 2], s3 = g_csr[e + 3];
                int s4 = g_csr[e + 4], s5 = g_csr[e + 5];
                int s6 = g_csr[e + 6], s7 = g_csr[e + 7];
                float4 v0 = in4[(size_t)s0 * 32 + lane];
                float4 v1 = in4[(size_t)s1 * 32 + lane];
                float4 v2 = in4[(size_t)s2 * 32 + lane];
                float4 v3 = in4[(size_t)s3 * 32 + lane];
                float4 v4 = in4[(size_t)s4 * 32 + lane];
                float4 v5 = in4[(size_t)s5 * 32 + lane];
                float4 v6 = in4[(size_t)s6 * 32 + lane];
                float4 v7 = in4[(size_t)s7 * 32 + lane];
                acc.x += ((v0.x + v1.x) + (v2.x + v3.x)) + ((v4.x + v5.x) + (v6.x + v7.x));
                acc.y += ((v0.y + v1.y) + (v2.y + v3.y)) + ((v4.y + v5.y) + (v6.y + v7.y));
                acc.z += ((v0.z + v1.z) + (v2.z + v3.z)) + ((v4.z + v5.z) + (v6.z + v7.z));
                acc.w += ((v0.w + v1.w) + (v2.w + v3.w)) + ((v4.w + v5.w) + (v6.w + v7.w));
            }
            for (; e < end; e++) {
                int s0 = g_csr[e];
                float4 v0 = in4[(size_t)s0 * 32 + lane];
                acc.x += v0.x; acc.y += v0.y; acc.z += v0.z; acc.w += v0.w;
            }
        }
        *(float4*)(sT + ln * F + lane * 4) = acc;
    }
    cp_wait1();            // W1 resident (group 0 drained)
    __syncthreads();

    // ---- Phase B: sH = relu(sT @ W1 + b1), f32x2 accumulation ----
    int tx = tid & 31;     // cols tx*4 .. tx*4+3
    int ty = tid >> 5;     // nodes ty*8 .. ty*8+7
    {
        unsigned long long acc[8][4];
        #pragma unroll
        for (int i = 0; i < 8; i++)
            #pragma unroll
            for (int j = 0; j < 4; j++) acc[i][j] = 0ULL;
        const float* tb = sT + (ty * 8) * F;
        const float* wb = sW1 + tx * 4;
        #pragma unroll 4
        for (int k = 0; k < F; k += 2) {
            float4 wa = *(const float4*)(wb + k * F);
            float4 wc = *(const float4*)(wb + (k + 1) * F);
            unsigned long long w0 = pk2(wa.x, wc.x);
            unsigned long long w1 = pk2(wa.y, wc.y);
            unsigned long long w2 = pk2(wa.z, wc.z);
            unsigned long long w3 = pk2(wa.w, wc.w);
            #pragma unroll
            for (int i = 0; i < 8; i++) {
                unsigned long long t2 = *(const unsigned long long*)(tb + i * F + k);
                fma2(acc[i][0], t2, w0);
                fma2(acc[i][1], t2, w1);
                fma2(acc[i][2], t2, w2);
                fma2(acc[i][3], t2, w3);
            }
        }
        float4 bv = *(const float4*)(b1 + tx * 4);
        #pragma unroll
        for (int i = 0; i < 8; i++) {
            float4 o;
            o.x = fmaxf(fold2(acc[i][0]) + bv.x, 0.f);
            o.y = fmaxf(fold2(acc[i][1]) + bv.y, 0.f);
            o.z = fmaxf(fold2(acc[i][2]) + bv.z, 0.f);
            o.w = fmaxf(fold2(acc[i][3]) + bv.w, 0.f);
            *(float4*)(sH + (ty * 8 + i) * F + tx * 4) = o;
        }
    }
    cp_wait0();            // W2 / w32 resident
    __syncthreads();

    if (!last) {
        // ---- Phase C: outF = sH @ W2 + b2 ----
        unsigned long long acc[8][4];
        #pragma unroll
        for (int i = 0; i < 8; i++)
            #pragma unroll
            for (int j = 0; j < 4; j++) acc[i][j] = 0ULL;
        const float* tb = sH + (ty * 8) * F;
        const float* wb = sW2 + tx * 4;
        #pragma unroll 4
        for (int k = 0; k < F; k += 2) {
            float4 wa = *(const float4*)(wb + k * F);
            float4 wc = *(const float4*)(wb + (k + 1) * F);
            unsigned long long w0 = pk2(wa.x, wc.x);
            unsigned long long w1 = pk2(wa.y, wc.y);
            unsigned long long w2 = pk2(wa.z, wc.z);
            unsigned long long w3 = pk2(wa.w, wc.w);
            #pragma unroll
            for (int i = 0; i < 8; i++) {
                unsigned long long t2 = *(const unsigned long long*)(tb + i * F + k);
                fma2(acc[i][0], t2, w0);
                fma2(acc[i][1], t2, w1);
                fma2(acc[i][2], t2, w2);
                fma2(acc[i][3], t2, w3);
            }
        }
        float4 bv = *(const float4*)(b2 + tx * 4);
        #pragma unroll
        for (int i = 0; i < 8; i++) {
            int n = nbase + ty * 8 + i;
            if (n < N_NODES) {
                float4 o;
                o.x = fold2(acc[i][0]) + bv.x;
                o.y = fold2(acc[i][1]) + bv.y;
                o.z = fold2(acc[i][2]) + bv.z;
                o.w = fold2(acc[i][3]) + bv.w;
                *(float4*)(outF + (size_t)n * F + tx * 4) = o;
            }
        }
    } else {
        // ---- Phase C': outS[n] = sH[n,:] . w32 + b32 ----
        float bb = b32[0];
        float4 wv = *(const float4*)(sW2 + lane * 4);
        #pragma unroll 1
        for (int i = 0; i < 8; i++) {
            int ln = w * 8 + i;
            int node = nbase + ln;
            float4 v = *(const float4*)(sH + ln * F + lane * 4);
            float s = v.x * wv.x + v.y * wv.y + v.z * wv.z + v.w * wv.w;
            #pragma unroll
            for (int o = 16; o; o >>= 1) s += __shfl_down_sync(0xffffffffu, s, o);
            if (lane == 0 && node < N_NODES) outS[node] = s + bb;
        }
    }
}

// ---------------- launch ---------------------------------------------------------
extern "C" void kernel_launch(void* const* d_in, const int* in_sizes, int n_in,
                              void* d_out, int out_size) {
    const float* x = (const float*)d_in[0];
    const void* ei = d_in[1];
    const float* w11 = (const float*)d_in[2];
    const float* b11 = (const float*)d_in[3];
    const float* w12 = (const float*)d_in[4];
    const float* b12 = (const float*)d_in[5];
    const float* w21 = (const float*)d_in[6];
    const float* b21 = (const float*)d_in[7];
    const float* w22 = (const float*)d_in[8];
    const float* b22 = (const float*)d_in[9];
    const float* w31 = (const float*)d_in[10];
    const float* b31 = (const float*)d_in[11];
    const float* w32 = (const float*)d_in[12];
    const float* b32 = (const float*)d_in[13];
    float* out = (float*)d_out;

    static int smem_set = 0;
    const int SMEM = (2 * F * F + 2 * TILE * F) * (int)sizeof(float); // 224 KB
    if (!smem_set) {
        cudaFuncSetAttribute(k_layer, cudaFuncAttributeMaxDynamicSharedMemorySize, SMEM);
        smem_set = 1;
    }

    // CSR build: launches 1..5, so launch 6 (first k_layer) is ncu's capture
    k_count<<<N_EDGES / 256, 256>>>(ei);
    k_scan1<<<SCAN_B, 512>>>();
    k_scan2<<<1, 256>>>();
    k_scan3<<<SCAN_B, 512>>>();
    k_fill<<<N_EDGES / 256, 256>>>(ei);

    k_layer<<<LAYER_BLOCKS, THREADS, SMEM>>>(x, w11, b11, w12, b12, 0, 1, b32, out);
    k_layer<<<LAYER_BLOCKS, THREADS, SMEM>>>(x, w21, b21, w22, b22, 1, 2, b32, out);
    k_layer<<<LAYER_BLOCKS, THREADS, SMEM>>>(x, w31, b31, w32, b32, 2, 3, b32, out);
}

// round 6
// speedup vs baseline: 1.8909x; 1.8909x over previous
#include <cuda_runtime.h>
#include <cuda_bf16.h>
#include <cstdint>

#define N_NODES 100000
#define N_EDGES 1600000
#define F 128
#define SCAN_B 196      // ceil(100001 / 512)
#define GEMM_BLOCKS ((N_NODES + 127) / 128)   // 782

// ---------------- scratch (static device globals; no cudaMalloc) ------------
__device__ __align__(16) int g_cnt[N_NODES + 1];   // zero-init; scan1 re-zeroes
__device__ __align__(16) int g_off[N_NODES + 1];
__device__ __align__(16) int g_cur[N_NODES];
__device__ __align__(16) int g_csr[N_EDGES];
__device__ __align__(16) int g_part[SCAN_B];
__device__ __align__(16) float g_t[(size_t)N_NODES * F]; // agg out
__device__ __align__(16) float g_m[(size_t)N_NODES * F]; // gemm1 out
__device__ __align__(16) float g_h[(size_t)N_NODES * F]; // layer out
// pre-split, transposed (Wt[n][k]), XOR-swizzled weights: [slot][hi/lo][128*128]
__device__ __align__(16) __nv_bfloat16 g_wp[5][2][F * F];

// ---------------- helpers -------------------------------------------------------
__device__ __forceinline__ unsigned pkbf2(float lo, float hi) {
    unsigned r;
    asm("cvt.rn.bf16x2.f32 %0, %1, %2;" : "=r"(r) : "f"(hi), "f"(lo));
    return r;   // low 16 bits = lo, high 16 bits = hi
}
__device__ __forceinline__ unsigned s2u(const void* p) {
    unsigned a;
    asm("{ .reg .u64 t; cvta.to.shared.u64 t, %1; cvt.u32.u64 %0, t; }"
        : "=r"(a) : "l"(p));
    return a;
}
__device__ __forceinline__ void cp16(unsigned smem_addr, const void* gptr) {
    asm volatile("cp.async.cg.shared.global [%0], [%1], 16;" ::
                 "r"(smem_addr), "l"(gptr));
}
__device__ __forceinline__ void cp_commit() { asm volatile("cp.async.commit_group;"); }
__device__ __forceinline__ void cp_wait0()  { asm volatile("cp.async.wait_group 0;"); }

__device__ __forceinline__ void mma16816(float* d, const unsigned* a,
                                         const unsigned* b) {
    asm("mma.sync.aligned.m16n8k16.row.col.f32.bf16.bf16.f32 "
        "{%0,%1,%2,%3}, {%4,%5,%6,%7}, {%8,%9}, {%0,%1,%2,%3};"
        : "+f"(d[0]), "+f"(d[1]), "+f"(d[2]), "+f"(d[3])
        : "r"(a[0]), "r"(a[1]), "r"(a[2]), "r"(a[3]), "r"(b[0]), "r"(b[1]));
}

// swizzled 32-bit word index within a 128-col bf16 row (64 words/row)
__device__ __forceinline__ int swz(int row, int w) {
    return row * 64 + (w ^ ((row & 7) << 2));
}

// ---------------- edge dtype: block-local detection ---------------------------
__device__ __forceinline__ int block_is64(const void* ei, int e) {
    unsigned hw = ((const unsigned*)ei)[2 * e + 1];
    int any = __syncthreads_or(hw != 0u);
    return any ? 0 : 1;
}

// ---------------- CSR build ----------------------------------------------------
__global__ void k_count(const void* __restrict__ ei) {
    int e = blockIdx.x * 256 + threadIdx.x;
    int is64 = block_is64(ei, e);
    int d = is64 ? (int)(((const long long*)ei)[N_EDGES + e])
                 : ((const int*)ei)[N_EDGES + e];
    atomicAdd(&g_cnt[d + 1], 1);
}

__global__ void k_scan1() {
    __shared__ int wsum[16];
    int tid = threadIdx.x;
    int i = blockIdx.x * 512 + tid;
    int lane = tid & 31, w = tid >> 5;
    int s = (i <= N_NODES) ? g_cnt[i] : 0;
    if (i <= N_NODES) g_cnt[i] = 0;                   // restore invariant
    #pragma unroll
    for (int o = 1; o < 32; o <<= 1) {
        int t = __shfl_up_sync(0xffffffffu, s, o);
        if (lane >= o) s += t;
    }
    if (lane == 31) wsum[w] = s;
    __syncthreads();
    if (w == 0) {
        int ws = (lane < 16) ? wsum[lane] : 0;
        #pragma unroll
        for (int o = 1; o < 16; o <<= 1) {
            int t = __shfl_up_sync(0xffffffffu, ws, o);
            if (lane >= o) ws += t;
        }
        if (lane < 16) wsum[lane] = ws;
    }
    __syncthreads();
    int incl = s + (w > 0 ? wsum[w - 1] : 0);
    if (i <= N_NODES) g_off[i] = incl;
    if (tid == 511) g_part[blockIdx.x] = incl;
}

__global__ void k_scan2() {
    __shared__ int wsum[8];
    int tid = threadIdx.x;
    int lane = tid & 31, w = tid >> 5;
    int s = (tid < SCAN_B) ? g_part[tid] : 0;
    #pragma unroll
    for (int o = 1; o < 32; o <<= 1) {
        int t = __shfl_up_sync(0xffffffffu, s, o);
        if (lane >= o) s += t;
    }
    if (lane == 31) wsum[w] = s;
    __syncthreads();
    if (w == 0) {
        int ws = (lane < 8) ? wsum[lane] : 0;
        #pragma unroll
        for (int o = 1; o < 8; o <<= 1) {
            int t = __shfl_up_sync(0xffffffffu, ws, o);
            if (lane >= o) ws += t;
        }
        if (lane < 8) wsum[lane] = ws;
    }
    __syncthreads();
    int incl = s + (w > 0 ? wsum[w - 1] : 0);
    if (tid < SCAN_B) g_part[tid] = incl;
}

__global__ void k_scan3() {
    int b = blockIdx.x;
    int i = b * 512 + threadIdx.x;
    if (i <= N_NODES) {
        int v = g_off[i] + (b > 0 ? g_part[b - 1] : 0);
        g_off[i] = v;
        if (i < N_NODES) g_cur[i] = v;
    }
}

__global__ void k_fill(const void* __restrict__ ei) {
    int e = blockIdx.x * 256 + threadIdx.x;
    int is64 = block_is64(ei, e);
    int s, d;
    if (is64) {
        s = (int)(((const long long*)ei)[e]);
        d = (int)(((const long long*)ei)[N_EDGES + e]);
    } else {
        s = ((const int*)ei)[e];
        d = ((const int*)ei)[N_EDGES + e];
    }
    int p = atomicAdd(&g_cur[d], 1);
    g_csr[p] = s;
}

// ---------------- aggregation: g_t[i] = in[i] + sum_{j->i} in[j] ---------------
__global__ void k_agg(const float* __restrict__ x, int layer) {
    const float* in = (layer == 0) ? x : (const float*)g_h;
    int w = (blockIdx.x * blockDim.x + threadIdx.x) >> 5;
    if (w >= N_NODES) return;
    int lane = threadIdx.x & 31;
    const float4* xin = (const float4*)in;
    float4 acc = xin[(size_t)w * 32 + lane];
    int e = g_off[w];
    int end = g_off[w + 1];
    for (; e + 4 <= end; e += 4) {
        int s0 = g_csr[e], s1 = g_csr[e + 1], s2 = g_csr[e + 2], s3 = g_csr[e + 3];
        float4 v0 = xin[(size_t)s0 * 32 + lane];
        float4 v1 = xin[(size_t)s1 * 32 + lane];
        float4 v2 = xin[(size_t)s2 * 32 + lane];
        float4 v3 = xin[(size_t)s3 * 32 + lane];
        acc.x += (v0.x + v1.x) + (v2.x + v3.x);
        acc.y += (v0.y + v1.y) + (v2.y + v3.y);
        acc.z += (v0.z + v1.z) + (v2.z + v3.z);
        acc.w += (v0.w + v1.w) + (v2.w + v3.w);
    }
    for (; e < end; e++) {
        int s0 = g_csr[e];
        float4 v0 = xin[(size_t)s0 * 32 + lane];
        acc.x += v0.x; acc.y += v0.y; acc.z += v0.z; acc.w += v0.w;
    }
    ((float4*)g_t)[(size_t)w * 32 + lane] = acc;
}

// ---------------- weight prep: W[k][j] -> Wt_hi/lo[n=j][k], swizzled ------------
__global__ void k_wprep(const float* __restrict__ w11, const float* __restrict__ w12,
                        const float* __restrict__ w21, const float* __restrict__ w22,
                        const float* __restrict__ w31) {
    const float* ws[5] = {w11, w12, w21, w22, w31};
    const float* W = ws[blockIdx.x];
    __nv_bfloat16* dhi = &g_wp[blockIdx.x][0][0];
    __nv_bfloat16* dlo = &g_wp[blockIdx.x][1][0];
    for (int idx = threadIdx.x; idx < F * F; idx += blockDim.x) {
        int n = idx >> 7, k = idx & 127;
        float v = W[k * F + n];
        __nv_bfloat16 h = __float2bfloat16(v);
        float l = v - __bfloat162float(h);
        int e = swz(n, k >> 1) * 2 + (k & 1);
        dhi[e] = h;
        dlo[e] = __float2bfloat16(l);
    }
}

// ---------------- tensor-core GEMM: out = act(in @ W + b), tile 128x128 --------
// smem: Ahi[128*128 bf16] Alo Bhi Blo + bias[128 f32] = 131584 B
#define SM_TOT (4 * F * F * 2 + F * 4)
__global__ void __launch_bounds__(256, 1)
k_gemm_mma(int src_sel, int slot, const float* __restrict__ bias,
           int do_relu, int dst_sel) {
    extern __shared__ __align__(16) char smem[];
    __nv_bfloat16* sAhi = (__nv_bfloat16*)smem;
    __nv_bfloat16* sAlo = sAhi + F * F;
    __nv_bfloat16* sBhi = sAlo + F * F;      // Wt hi (then lo right after)
    float* sBias = (float*)(sBhi + 2 * F * F);

    const float* in = src_sel ? (const float*)g_m : (const float*)g_t;
    float* out = dst_sel ? (float*)g_h : (float*)g_m;

    int tid = threadIdx.x;
    int lane = tid & 31, wid = tid >> 5;
    int nbase = blockIdx.x * 128;

    // ---- B (Wt hi+lo, pre-swizzled): linear 64 KB cp.async ----
    unsigned sB = s2u(sBhi);
    const char* gb = (const char*)&g_wp[slot][0][0];
    #pragma unroll
    for (int i = 0; i < 16; i++)
        cp16(sB + (tid + i * 256) * 16, gb + (size_t)(tid + i * 256) * 16);
    cp_commit();
    if (tid < F) sBias[tid] = bias[tid];

    // ---- A: load rows, split hi/lo, store swizzled ----
    {
        int r = tid >> 1;                       // row 0..127
        int node = nbase + r;
        int cbase = (tid & 1) * 8;              // 8 uint4 chunks of 16
        const float4* src4 = (const float4*)in + (size_t)node * 32;
        uint4* dAhi = (uint4*)sAhi;
        uint4* dAlo = (uint4*)sAlo;
        #pragma unroll
        for (int c = cbase; c < cbase + 8; c++) {
            float4 fa, fb;
            if (node < N_NODES) { fa = src4[2 * c]; fb = src4[2 * c + 1]; }
            else { fa = make_float4(0.f, 0.f, 0.f, 0.f); fb = fa; }
            float v[8] = {fa.x, fa.y, fa.z, fa.w, fb.x, fb.y, fb.z, fb.w};
            unsigned hu[8]; float lv[8];
            #pragma unroll
            for (int e = 0; e < 8; e++) {
                __nv_bfloat16 h = __float2bfloat16(v[e]);
                hu[e] = __bfloat16_as_ushort(h);
                lv[e] = v[e] - __bfloat162float(h);
            }
            uint4 HW, LW;
            HW.x = (hu[1] << 16) | hu[0];  HW.y = (hu[3] << 16) | hu[2];
            HW.z = (hu[5] << 16) | hu[4];  HW.w = (hu[7] << 16) | hu[6];
            LW.x = pkbf2(lv[0], lv[1]);    LW.y = pkbf2(lv[2], lv[3]);
            LW.z = pkbf2(lv[4], lv[5]);    LW.w = pkbf2(lv[6], lv[7]);
            int dst = r * 16 + (c ^ (r & 7));   // uint4-granular swizzle
            dAhi[dst] = HW;
            dAlo[dst] = LW;
        }
    }
    cp_wait0();
    __syncthreads();

    const unsigned* uAhi = (const unsigned*)sAhi;
    const unsigned* uAlo = (const unsigned*)sAlo;
    const unsigned* uBhi = (const unsigned*)sBhi;
    const unsigned* uBlo = uBhi + F * F / 2;

    // ---- main loop: warp computes rows wid*16..+15, all 128 cols ----
    float acc[16][4];
    #pragma unroll
    for (int i = 0; i < 16; i++)
        #pragma unroll
        for (int j = 0; j < 4; j++) acc[i][j] = 0.f;

    int g = lane >> 2;        // group id 0..7
    int t = lane & 3;         // thread in group
    int m0 = wid * 16 + g;    // fragment row (lower 8)

    #pragma unroll
    for (int s = 0; s < 8; s++) {
        int w0 = 8 * s + t, w1 = 8 * s + t + 4;
        unsigned ahi[4], alo[4];
        ahi[0] = uAhi[swz(m0, w0)];     ahi[1] = uAhi[swz(m0 + 8, w0)];
        ahi[2] = uAhi[swz(m0, w1)];     ahi[3] = uAhi[swz(m0 + 8, w1)];
        alo[0] = uAlo[swz(m0, w0)];     alo[1] = uAlo[swz(m0 + 8, w0)];
        alo[2] = uAlo[swz(m0, w1)];     alo[3] = uAlo[swz(m0 + 8, w1)];
        #pragma unroll
        for (int nt = 0; nt < 16; nt++) {
            int n0 = nt * 8 + g;
            unsigned bh[2], bl[2];
            bh[0] = uBhi[swz(n0, w0)];  bh[1] = uBhi[swz(n0, w1)];
            bl[0] = uBlo[swz(n0, w0)];  bl[1] = uBlo[swz(n0, w1)];
            mma16816(acc[nt], ahi, bh);
            mma16816(acc[nt], ahi, bl);
            mma16816(acc[nt], alo, bh);
        }
    }

    // ---- epilogue: D rows m0 / m0+8, cols nt*8 + 2t, 2t+1 ----
    int node0 = nbase + m0;
    int node1 = node0 + 8;
    #pragma unroll
    for (int nt = 0; nt < 16; nt++) {
        int col = nt * 8 + 2 * t;
        float bx = sBias[col], by = sBias[col + 1];
        float2 o0, o1;
        o0.x = acc[nt][0] + bx;  o0.y = acc[nt][1] + by;
        o1.x = acc[nt][2] + bx;  o1.y = acc[nt][3] + by;
        if (do_relu) {
            o0.x = fmaxf(o0.x, 0.f); o0.y = fmaxf(o0.y, 0.f);
            o1.x = fmaxf(o1.x, 0.f); o1.y = fmaxf(o1.y, 0.f);
        }
        if (node0 < N_NODES) *(float2*)(out + (size_t)node0 * F + col) = o0;
        if (node1 < N_NODES) *(float2*)(out + (size_t)node1 * F + col) = o1;
    }
}

// ---------------- final 128 -> 1 dot per node -----------------------------------
__global__ void k_dot(const float* __restrict__ w, const float* __restrict__ b,
                      float* __restrict__ out) {
    __shared__ __align__(16) float sw[F];
    if (threadIdx.x < F) sw[threadIdx.x] = w[threadIdx.x];
    __syncthreads();
    int node = (blockIdx.x * blockDim.x + threadIdx.x) >> 5;
    if (node >= N_NODES) return;
    int lane = threadIdx.x & 31;
    float4 v = ((const float4*)g_m)[(size_t)node * 32 + lane];
    float4 wv = ((const float4*)sw)[lane];
    float s = v.x * wv.x + v.y * wv.y + v.z * wv.z + v.w * wv.w;
    #pragma unroll
    for (int o = 16; o; o >>= 1) s += __shfl_down_sync(0xffffffffu, s, o);
    if (lane == 0) out[node] = s + b[0];
}

// ---------------- launch ---------------------------------------------------------
extern "C" void kernel_launch(void* const* d_in, const int* in_sizes, int n_in,
                              void* d_out, int out_size) {
    const float* x = (const float*)d_in[0];
    const void* ei = d_in[1];
    const float* w11 = (const float*)d_in[2];
    const float* b11 = (const float*)d_in[3];
    const float* w12 = (const float*)d_in[4];
    const float* b12 = (const float*)d_in[5];
    const float* w21 = (const float*)d_in[6];
    const float* b21 = (const float*)d_in[7];
    const float* w22 = (const float*)d_in[8];
    const float* b22 = (const float*)d_in[9];
    const float* w31 = (const float*)d_in[10];
    const float* b31 = (const float*)d_in[11];
    const float* w32 = (const float*)d_in[12];
    const float* b32 = (const float*)d_in[13];
    float* out = (float*)d_out;

    static int smem_set = 0;
    if (!smem_set) {
        cudaFuncSetAttribute(k_gemm_mma, cudaFuncAttributeMaxDynamicSharedMemorySize,
                             SM_TOT);
        smem_set = 1;
    }

    const int AGG_BLOCKS = (N_NODES * 32 + 255) / 256;   // warp per node

    // CSR build (launches 1-5), then k_agg is launch 6 -> ncu capture target
    k_count<<<N_EDGES / 256, 256>>>(ei);
    k_scan1<<<SCAN_B, 512>>>();
    k_scan2<<<1, 256>>>();
    k_scan3<<<SCAN_B, 512>>>();
    k_fill<<<N_EDGES / 256, 256>>>(ei);

    k_agg<<<AGG_BLOCKS, 256>>>(x, 0);
    k_wprep<<<5, 256>>>(w11, w12, w21, w22, w31);

    // layer 1
    k_gemm_mma<<<GEMM_BLOCKS, 256, SM_TOT>>>(0, 0, b11, 1, 0);  // g_t->g_m relu
    k_gemm_mma<<<GEMM_BLOCKS, 256, SM_TOT>>>(1, 1, b12, 0, 1);  // g_m->g_h
    // layer 2
    k_agg<<<AGG_BLOCKS, 256>>>(x, 1);
    k_gemm_mma<<<GEMM_BLOCKS, 256, SM_TOT>>>(0, 2, b21, 1, 0);
    k_gemm_mma<<<GEMM_BLOCKS, 256, SM_TOT>>>(1, 3, b22, 0, 1);
    // layer 3
    k_agg<<<AGG_BLOCKS, 256>>>(x, 2);
    k_gemm_mma<<<GEMM_BLOCKS, 256, SM_TOT>>>(0, 4, b31, 1, 0);
    k_dot<<<AGG_BLOCKS, 256>>>(w32, b32, out);
}

// round 7
// speedup vs baseline: 2.0814x; 1.1007x over previous
#include <cuda_runtime.h>
#include <cuda_bf16.h>
#include <cstdint>

#define N_NODES 100000
#define N_EDGES 1600000
#define F 128
#define SCAN_B 196      // ceil(100001 / 512)
#define GEMM_BLOCKS ((N_NODES + 127) / 128)   // 782

// ---------------- scratch (static device globals; no cudaMalloc) ------------
__device__ __align__(16) int g_cnt[N_NODES + 1];   // zero-init; scan re-zeroes
__device__ __align__(16) int g_off[N_NODES + 1];
__device__ __align__(16) int g_cur[N_NODES];
__device__ __align__(16) int g_csr[N_EDGES];
__device__ __align__(16) unsigned long long g_desc[SCAN_B];  // lookback state
__device__ __align__(16) float g_t[(size_t)N_NODES * F]; // agg out
__device__ __align__(16) float g_m[(size_t)N_NODES * F]; // relu(H) out
__device__ __align__(16) float g_wc[2][F * F];           // W12@W21, W22@W31
__device__ __align__(16) float g_bc[2][F];               // b12@W21, b22@W31
// pre-split, transposed (Wt[n][k]), XOR-swizzled weights: [slot][hi/lo][128*128]
__device__ __align__(16) __nv_bfloat16 g_wp[3][2][F * F];

// ---------------- helpers -------------------------------------------------------
__device__ __forceinline__ unsigned pkbf2(float lo, float hi) {
    unsigned r;
    asm("cvt.rn.bf16x2.f32 %0, %1, %2;" : "=r"(r) : "f"(hi), "f"(lo));
    return r;
}
__device__ __forceinline__ unsigned s2u(const void* p) {
    unsigned a;
    asm("{ .reg .u64 t; cvta.to.shared.u64 t, %1; cvt.u32.u64 %0, t; }"
        : "=r"(a) : "l"(p));
    return a;
}
__device__ __forceinline__ void cp16(unsigned smem_addr, const void* gptr) {
    asm volatile("cp.async.cg.shared.global [%0], [%1], 16;" ::
                 "r"(smem_addr), "l"(gptr));
}
__device__ __forceinline__ void cp_commit() { asm volatile("cp.async.commit_group;"); }
__device__ __forceinline__ void cp_wait0()  { asm volatile("cp.async.wait_group 0;"); }

__device__ __forceinline__ void mma16816(float* d, const unsigned* a,
                                         const unsigned* b) {
    asm("mma.sync.aligned.m16n8k16.row.col.f32.bf16.bf16.f32 "
        "{%0,%1,%2,%3}, {%4,%5,%6,%7}, {%8,%9}, {%0,%1,%2,%3};"
        : "+f"(d[0]), "+f"(d[1]), "+f"(d[2]), "+f"(d[3])
        : "r"(a[0]), "r"(a[1]), "r"(a[2]), "r"(a[3]), "r"(b[0]), "r"(b[1]));
}

// swizzled 32-bit word index within a 128-col bf16 row (64 words/row)
__device__ __forceinline__ int swz(int row, int w) {
    return row * 64 + (w ^ ((row & 7) << 2));
}

// ---------------- edge dtype: block-local detection ---------------------------
__device__ __forceinline__ int block_is64(const void* ei, int e) {
    unsigned hw = ((const unsigned*)ei)[2 * e + 1];
    int any = __syncthreads_or(hw != 0u);
    return any ? 0 : 1;
}

// ---------------- CSR build ----------------------------------------------------
__global__ void k_count(const void* __restrict__ ei) {
    if (blockIdx.x == 0 && threadIdx.x < SCAN_B) g_desc[threadIdx.x] = 0ULL;
    int e = blockIdx.x * 256 + threadIdx.x;
    int is64 = block_is64(ei, e);
    int d = is64 ? (int)(((const long long*)ei)[N_EDGES + e])
                 : ((const int*)ei)[N_EDGES + e];
    atomicAdd(&g_cnt[d + 1], 1);
}

// single-kernel decoupled-lookback scan over g_cnt[0..N_NODES] -> g_off, g_cur
__global__ void k_scan_lb() {
    __shared__ int wsum[16];
    __shared__ int s_exc;
    int tid = threadIdx.x, b = blockIdx.x;
    int i = b * 512 + tid;
    int lane = tid & 31, w = tid >> 5;
    int v = (i <= N_NODES) ? g_cnt[i] : 0;
    if (i <= N_NODES) g_cnt[i] = 0;                   // restore invariant
    int s = v;
    #pragma unroll
    for (int o = 1; o < 32; o <<= 1) {
        int t = __shfl_up_sync(0xffffffffu, s, o);
        if (lane >= o) s += t;
    }
    if (lane == 31) wsum[w] = s;
    __syncthreads();
    if (w == 0) {
        int ws = (lane < 16) ? wsum[lane] : 0;
        #pragma unroll
        for (int o = 1; o < 16; o <<= 1) {
            int t = __shfl_up_sync(0xffffffffu, ws, o);
            if (lane >= o) ws += t;
        }
        if (lane < 16) wsum[lane] = ws;
    }
    __syncthreads();
    int incl = s + (w > 0 ? wsum[w - 1] : 0);
    int total = wsum[15];
    if (tid == 0) {
        unsigned long long pub =
            ((unsigned long long)(b == 0 ? 2u : 1u) << 32) | (unsigned)total;
        atomicExch(&g_desc[b], pub);
    }
    int exc = 0;
    if (b > 0) {
        if (tid == 0) {
            int p = b - 1, run = 0;
            while (true) {
                unsigned long long d = atomicAdd(&g_desc[p], 0ULL);
                unsigned f = (unsigned)(d >> 32);
                if (f == 0u) continue;
                run += (int)(d & 0xffffffffu);
                if (f == 2u) break;
                p--;
            }
            s_exc = run;
            atomicExch(&g_desc[b], (2ULL << 32) | (unsigned)(run + total));
        }
        __syncthreads();
        exc = s_exc;
    }
    if (i <= N_NODES) {
        int val = exc + incl;
        g_off[i] = val;
        if (i < N_NODES) g_cur[i] = val;
    }
}

__global__ void k_fill(const void* __restrict__ ei) {
    int e = blockIdx.x * 256 + threadIdx.x;
    int is64 = block_is64(ei, e);
    int s, d;
    if (is64) {
        s = (int)(((const long long*)ei)[e]);
        d = (int)(((const long long*)ei)[N_EDGES + e]);
    } else {
        s = ((const int*)ei)[e];
        d = ((const int*)ei)[N_EDGES + e];
    }
    int p = atomicAdd(&g_cur[d], 1);
    g_csr[p] = s;
}

// ---------------- aggregation: g_t[i] = in[i] + sum_{j->i} in[j] ---------------
__global__ void k_agg(const float* __restrict__ x, int layer) {
    const float* in = (layer == 0) ? x : (const float*)g_m;
    int w = (blockIdx.x * blockDim.x + threadIdx.x) >> 5;
    if (w >= N_NODES) return;
    int lane = threadIdx.x & 31;
    const float4* xin = (const float4*)in;
    float4 acc = xin[(size_t)w * 32 + lane];
    int e = g_off[w];
    int end = g_off[w + 1];
    for (; e + 4 <= end; e += 4) {
        int s0 = g_csr[e], s1 = g_csr[e + 1], s2 = g_csr[e + 2], s3 = g_csr[e + 3];
        float4 v0 = xin[(size_t)s0 * 32 + lane];
        float4 v1 = xin[(size_t)s1 * 32 + lane];
        float4 v2 = xin[(size_t)s2 * 32 + lane];
        float4 v3 = xin[(size_t)s3 * 32 + lane];
        acc.x += (v0.x + v1.x) + (v2.x + v3.x);
        acc.y += (v0.y + v1.y) + (v2.y + v3.y);
        acc.z += (v0.z + v1.z) + (v2.z + v3.z);
        acc.w += (v0.w + v1.w) + (v2.w + v3.w);
    }
    for (; e < end; e++) {
        int s0 = g_csr[e];
        float4 v0 = xin[(size_t)s0 * 32 + lane];
        acc.x += v0.x; acc.y += v0.y; acc.z += v0.z; acc.w += v0.w;
    }
    ((float4*)g_t)[(size_t)w * 32 + lane] = acc;
}

// ---------------- combined weights: Wc = A@B (fp32), bc = bA@B ------------------
// prod 0: A=w12, bA=b12, B=w21 ; prod 1: A=w22, bA=b22, B=w31
__global__ void k_wcombine(const float* __restrict__ w12, const float* __restrict__ b12,
                           const float* __restrict__ w21, const float* __restrict__ w22,
                           const float* __restrict__ b22, const float* __restrict__ w31) {
    int prod = blockIdx.x >> 3, rowg = blockIdx.x & 7;
    const float* A  = prod ? w22 : w12;
    const float* bA = prod ? b22 : b12;
    const float* B  = prod ? w31 : w21;
    float* C  = g_wc[prod];
    float* bc = g_bc[prod];
    for (int idx = threadIdx.x; idx < 16 * F; idx += blockDim.x) {
        int k = rowg * 16 + (idx >> 7);
        int j = idx & 127;
        float s = 0.f;
        #pragma unroll 4
        for (int m = 0; m < F; m++) s += A[k * F + m] * B[m * F + j];
        C[k * F + j] = s;
    }
    if (rowg == 0 && threadIdx.x < F) {
        int j = threadIdx.x;
        float s = 0.f;
        #pragma unroll 4
        for (int m = 0; m < F; m++) s += bA[m] * B[m * F + j];
        bc[j] = s;
    }
}

// ---------------- weight prep: W[k][j] -> Wt_hi/lo[n=j][k], swizzled ------------
// slot 0 = w11 (param), slot 1 = g_wc[0], slot 2 = g_wc[1]
__global__ void k_wprep(const float* __restrict__ w11) {
    const float* W = (blockIdx.x == 0) ? w11 : g_wc[blockIdx.x - 1];
    __nv_bfloat16* dhi = &g_wp[blockIdx.x][0][0];
    __nv_bfloat16* dlo = &g_wp[blockIdx.x][1][0];
    for (int idx = threadIdx.x; idx < F * F; idx += blockDim.x) {
        int n = idx >> 7, k = idx & 127;
        float v = W[k * F + n];
        __nv_bfloat16 h = __float2bfloat16(v);
        float l = v - __bfloat162float(h);
        int e = swz(n, k >> 1) * 2 + (k & 1);
        dhi[e] = h;
        dlo[e] = __float2bfloat16(l);
    }
}

// ---------------- tensor-core GEMM: H = relu(g_t @ W + bias), tile 128x128 ------
// bias[col] = bias1[col] + (1+deg_row)*g_bc[bc_sel-1][col]  (bc_sel=0: none)
// dot_mode: out[n] = H[n,:].w32 + b32 ; else g_m[n,:] = H[n,:]
#define SM_TOT (4 * F * F * 2 + 3 * F * 4)
__global__ void __launch_bounds__(256, 1)
k_gemm_mma(int slot, const float* __restrict__ bias1, int bc_sel, int dot_mode,
           const float* __restrict__ w32, const float* __restrict__ b32,
           float* __restrict__ outS) {
    extern __shared__ __align__(16) char smem[];
    __nv_bfloat16* sAhi = (__nv_bfloat16*)smem;
    __nv_bfloat16* sAlo = sAhi + F * F;
    __nv_bfloat16* sBhi = sAlo + F * F;      // Wt hi (lo right after)
    float* sBias1 = (float*)(sBhi + 2 * F * F);
    float* sBiasC = sBias1 + F;
    float* sW32   = sBiasC + F;

    const float* in = (const float*)g_t;
    float* out = (float*)g_m;

    int tid = threadIdx.x;
    int lane = tid & 31, wid = tid >> 5;
    int nbase = blockIdx.x * 128;

    // ---- B (Wt hi+lo, pre-swizzled): linear 64 KB cp.async ----
    unsigned sB = s2u(sBhi);
    const char* gb = (const char*)&g_wp[slot][0][0];
    #pragma unroll
    for (int i = 0; i < 16; i++)
        cp16(sB + (tid + i * 256) * 16, gb + (size_t)(tid + i * 256) * 16);
    cp_commit();
    if (tid < F) {
        sBias1[tid] = bias1[tid];
        sBiasC[tid] = bc_sel ? g_bc[bc_sel - 1][tid] : 0.f;
        sW32[tid]   = dot_mode ? w32[tid] : 0.f;
    }

    // ---- A: load rows from g_t, split hi/lo, store swizzled ----
    {
        int r = tid >> 1;                       // row 0..127
        int node = nbase + r;
        int cbase = (tid & 1) * 8;              // 8 uint4 chunks of 16
        const float4* src4 = (const float4*)in + (size_t)node * 32;
        uint4* dAhi = (uint4*)sAhi;
        uint4* dAlo = (uint4*)sAlo;
        #pragma unroll
        for (int c = cbase; c < cbase + 8; c++) {
            float4 fa, fb;
            if (node < N_NODES) { fa = src4[2 * c]; fb = src4[2 * c + 1]; }
            else { fa = make_float4(0.f, 0.f, 0.f, 0.f); fb = fa; }
            float v[8] = {fa.x, fa.y, fa.z, fa.w, fb.x, fb.y, fb.z, fb.w};
            unsigned hu[8]; float lv[8];
            #pragma unroll
            for (int e = 0; e < 8; e++) {
                __nv_bfloat16 h = __float2bfloat16(v[e]);
                hu[e] = __bfloat16_as_ushort(h);
                lv[e] = v[e] - __bfloat162float(h);
            }
            uint4 HW, LW;
            HW.x = (hu[1] << 16) | hu[0];  HW.y = (hu[3] << 16) | hu[2];
            HW.z = (hu[5] << 16) | hu[4];  HW.w = (hu[7] << 16) | hu[6];
            LW.x = pkbf2(lv[0], lv[1]);    LW.y = pkbf2(lv[2], lv[3]);
            LW.z = pkbf2(lv[4], lv[5]);    LW.w = pkbf2(lv[6], lv[7]);
            int dst = r * 16 + (c ^ (r & 7));   // uint4-granular swizzle
            dAhi[dst] = HW;
            dAlo[dst] = LW;
        }
    }
    cp_wait0();
    __syncthreads();

    const unsigned* uAhi = (const unsigned*)sAhi;
    const unsigned* uAlo = (const unsigned*)sAlo;
    const unsigned* uBhi = (const unsigned*)sBhi;
    const unsigned* uBlo = uBhi + F * F / 2;

    float acc[16][4];
    #pragma unroll
    for (int i = 0; i < 16; i++)
        #pragma unroll
        for (int j = 0; j < 4; j++) acc[i][j] = 0.f;

    int g = lane >> 2;        // group id 0..7
    int t = lane & 3;         // thread in group
    int m0 = wid * 16 + g;    // fragment row (lower 8)

    #pragma unroll
    for (int s = 0; s < 8; s++) {
        int w0 = 8 * s + t, w1 = 8 * s + t + 4;
        unsigned ahi[4], alo[4];
        ahi[0] = uAhi[swz(m0, w0)];     ahi[1] = uAhi[swz(m0 + 8, w0)];
        ahi[2] = uAhi[swz(m0, w1)];     ahi[3] = uAhi[swz(m0 + 8, w1)];
        alo[0] = uAlo[swz(m0, w0)];     alo[1] = uAlo[swz(m0 + 8, w0)];
        alo[2] = uAlo[swz(m0, w1)];     alo[3] = uAlo[swz(m0 + 8, w1)];
        #pragma unroll
        for (int nt = 0; nt < 16; nt++) {
            int n0 = nt * 8 + g;
            unsigned bh[2], bl[2];
            bh[0] = uBhi[swz(n0, w0)];  bh[1] = uBhi[swz(n0, w1)];
            bl[0] = uBlo[swz(n0, w0)];  bl[1] = uBlo[swz(n0, w1)];
            mma16816(acc[nt], ahi, bh);
            mma16816(acc[nt], ahi, bl);
            mma16816(acc[nt], alo, bh);
        }
    }

    // ---- epilogue ----
    int node0 = nbase + m0;
    int node1 = node0 + 8;
    float sc0 = 0.f, sc1 = 0.f;
    if (bc_sel) {
        if (node0 < N_NODES) sc0 = 1.f + (float)(g_off[node0 + 1] - g_off[node0]);
        if (node1 < N_NODES) sc1 = 1.f + (float)(g_off[node1 + 1] - g_off[node1]);
    }
    if (!dot_mode) {
        #pragma unroll
        for (int nt = 0; nt < 16; nt++) {
            int col = nt * 8 + 2 * t;
            float bx = sBias1[col], by = sBias1[col + 1];
            float cx = sBiasC[col], cy = sBiasC[col + 1];
            float2 o0, o1;
            o0.x = fmaxf(acc[nt][0] + bx + sc0 * cx, 0.f);
            o0.y = fmaxf(acc[nt][1] + by + sc0 * cy, 0.f);
            o1.x = fmaxf(acc[nt][2] + bx + sc1 * cx, 0.f);
            o1.y = fmaxf(acc[nt][3] + by + sc1 * cy, 0.f);
            if (node0 < N_NODES) *(float2*)(out + (size_t)node0 * F + col) = o0;
            if (node1 < N_NODES) *(float2*)(out + (size_t)node1 * F + col) = o1;
        }
    } else {
        float p0 = 0.f, p1 = 0.f;
        #pragma unroll
        for (int nt = 0; nt < 16; nt++) {
            int col = nt * 8 + 2 * t;
            float bx = sBias1[col], by = sBias1[col + 1];
            float cx = sBiasC[col], cy = sBiasC[col + 1];
            p0 += fmaxf(acc[nt][0] + bx + sc0 * cx, 0.f) * sW32[col]
                + fmaxf(acc[nt][1] + by + sc0 * cy, 0.f) * sW32[col + 1];
            p1 += fmaxf(acc[nt][2] + bx + sc1 * cx, 0.f) * sW32[col]
                + fmaxf(acc[nt][3] + by + sc1 * cy, 0.f) * sW32[col + 1];
        }
        p0 += __shfl_xor_sync(0xffffffffu, p0, 1);
        p0 += __shfl_xor_sync(0xffffffffu, p0, 2);
        p1 += __shfl_xor_sync(0xffffffffu, p1, 1);
        p1 += __shfl_xor_sync(0xffffffffu, p1, 2);
        if (t == 0) {
            float bb = b32[0];
            if (node0 < N_NODES) outS[node0] = p0 + bb;
            if (node1 < N_NODES) outS[node1] = p1 + bb;
        }
    }
}

// ---------------- launch ---------------------------------------------------------
extern "C" void kernel_launch(void* const* d_in, const int* in_sizes, int n_in,
                              void* d_out, int out_size) {
    const float* x = (const float*)d_in[0];
    const void* ei = d_in[1];
    const float* w11 = (const float*)d_in[2];
    const float* b11 = (const float*)d_in[3];
    const float* w12 = (const float*)d_in[4];
    const float* b12 = (const float*)d_in[5];
    const float* w21 = (const float*)d_in[6];
    const float* b21 = (const float*)d_in[7];
    const float* w22 = (const float*)d_in[8];
    const float* b22 = (const float*)d_in[9];
    const float* w31 = (const float*)d_in[10];
    const float* b31 = (const float*)d_in[11];
    const float* w32 = (const float*)d_in[12];
    const float* b32 = (const float*)d_in[13];
    float* out = (float*)d_out;

    static int smem_set = 0;
    if (!smem_set) {
        cudaFuncSetAttribute(k_gemm_mma, cudaFuncAttributeMaxDynamicSharedMemorySize,
                             SM_TOT);
        smem_set = 1;
    }

    const int AGG_BLOCKS = (N_NODES * 32 + 255) / 256;   // warp per node

    k_count<<<N_EDGES / 256, 256>>>(ei);      // 1 (also zeroes lookback state)
    k_scan_lb<<<SCAN_B, 512>>>();             // 2
    k_fill<<<N_EDGES / 256, 256>>>(ei);       // 3
    k_agg<<<AGG_BLOCKS, 256>>>(x, 0);         // 4  <- ncu capture target
    k_wcombine<<<16, 256>>>(w12, b12, w21, w22, b22, w31);
    k_wprep<<<3, 256>>>(w11);

    // H1 = relu(agg(x)@W11 + b11)
    k_gemm_mma<<<GEMM_BLOCKS, 256, SM_TOT>>>(0, b11, 0, 0, w32, b32, out);
    // H2 = relu(agg(H1)@Wc2 + (1+deg)bc2 + b21)
    k_agg<<<AGG_BLOCKS, 256>>>(x, 1);
    k_gemm_mma<<<GEMM_BLOCKS, 256, SM_TOT>>>(1, b21, 1, 0, w32, b32, out);
    // out = relu(agg(H2)@Wc3 + (1+deg)bc3 + b31) . w32 + b32
    k_agg<<<AGG_BLOCKS, 256>>>(x, 2);
    k_gemm_mma<<<GEMM_BLOCKS, 256, SM_TOT>>>(2, b31, 2, 1, w32, b32, out);
}